// round 4
// baseline (speedup 1.0000x reference)
#include <cuda_runtime.h>
#include <cstdint>

// Problem constants (fixed by the reference)
#define BB 32
#define TT 256
#define NN 1536
#define NI 768

// Sim config: ONE CTA per batch, 768 threads, 2 neurons/thread.
#define TPB   768
#define NPT   2
#define NWARP (TPB / 32)

// exp constants, correctly rounded fp32
#define AR0 0.13533528323661270f   // exp(-2)    : rise tau 0.5 (syn0, syn2, FF)
#define AR1 0.60653065971263342f   // exp(-0.5)  : rise tau 2   (syn1)
#define AD0 0.60653065971263342f   // exp(-0.5)  : decay tau 2  (syn0, FF)
#define AD1 0.99004983374916805f   // exp(-0.01) : decay tau 100(syn1)
#define AD2 0.81873075307798186f   // exp(-0.2)  : decay tau 5  (syn2)

// ------------------------- device scratch (statics; no allocs) -------------
__device__ float d_Wsc[NN * NN];             // weights * sf[ct[n]][ct[m]]
__device__ float d_WFsc[NI * NN];            // weights_FF * sfF[ct[m]]
__device__ float d_IF[(size_t)BB * TT * NN]; // precomputed FF drive
__device__ int   d_ffcnt[BB * TT];           // input spike counts per (b,t)
__device__ int   d_fflist[BB * TT][NI];      // byte offsets j*NN*4

// ------------------------- weight scaling ----------------------------------
__global__ void scale_k(const float* __restrict__ w, const float* __restrict__ wff,
                        const float* __restrict__ sf, const float* __restrict__ sff,
                        const int* __restrict__ ct) {
    int idx = blockIdx.x * 256 + threadIdx.x;
    if (idx < NN * NN) {
        int n = idx / NN, m = idx % NN;
        d_Wsc[idx] = w[idx] * sf[ct[n] * 2 + ct[m]];
    } else {
        int r = idx - NN * NN;
        if (r < NI * NN) {
            int m = r % NN;
            d_WFsc[r] = wff[r] * sff[ct[m]];   // ct_FF is all zeros -> row 0
        }
    }
}

// ------------------------- FF spike lists (ballot-ordered, byte offsets) ---
__global__ void ffl_k(const float* __restrict__ inp) {
    int bt = blockIdx.x;                      // bt = b*TT + t
    int lane = threadIdx.x;
    const float* row = inp + (size_t)bt * NI;
    int cnt = 0;
    for (int base = 0; base < NI; base += 32) {
        float v = row[base + lane];
        unsigned m = __ballot_sync(0xFFFFFFFFu, v > 0.5f);
        if (v > 0.5f) {
            int p = cnt + __popc(m & ((1u << lane) - 1u));
            d_fflist[bt][p] = (base + lane) * NN * 4;   // byte offset of row
        }
        cnt += __popc(m);
    }
    if (lane == 0) d_ffcnt[bt] = cnt;
}

// ------------------------- FF drive precompute ------------------------------
// CTA = (64-col tile, batch): slab 768x64 fp32 = 196KB stays L1-resident.
// 16 warps, each warp owns 16 timesteps; lanes cover 2 cols each (float2).
#define FCOLS 64
#define FTPB  512
__global__ void __launch_bounds__(FTPB, 2) ffpre_k() {
    int b  = blockIdx.y;
    int c0 = blockIdx.x * FCOLS;
    int w    = threadIdx.x >> 5;
    int lane = threadIdx.x & 31;
    const char* __restrict__ Wc =
        (const char*)d_WFsc + (size_t)(c0 + lane * 2) * 4;
#pragma unroll
    for (int ti = 0; ti < TT / 16; ti++) {
        int t  = w * 16 + ti;
        int bt = b * TT + t;
        int fc = d_ffcnt[bt];
        const int* __restrict__ lst = d_fflist[bt];
        float a0 = 0.f, a1 = 0.f, a2 = 0.f, a3 = 0.f;
        int e = 0;
#pragma unroll 4
        for (; e + 1 < fc; e += 2) {
            int o0 = lst[e], o1 = lst[e + 1];
            float2 v0 = *(const float2*)(Wc + o0);
            float2 v1 = *(const float2*)(Wc + o1);
            a0 += v0.x; a1 += v0.y; a2 += v1.x; a3 += v1.y;
        }
        if (e < fc) {
            float2 v = *(const float2*)(Wc + lst[e]);
            a0 += v.x; a1 += v.y;
        }
        *(float2*)&d_IF[(size_t)bt * NN + c0 + lane * 2] =
            make_float2(a0 + a2, a1 + a3);
    }
}

// ------------------------- main persistent simulator ------------------------
// grid = 32 (one CTA per batch), block = 768 (one thread per 2 neurons).
// Spike lists are CTA-local in shared memory; the only cross-thread sync is
// __syncthreads. Spike entries are byte offsets (j*NN*4) into d_Wsc.
__global__ void __launch_bounds__(TPB, 1)
sim_k(const int* __restrict__ ct, float* __restrict__ out) {
    const int b    = blockIdx.x;
    const int tid  = threadIdx.x;
    const int wid  = tid >> 5, lane = tid & 31;
    const int n0   = tid * NPT;

    // double-buffered type-split spike lists (byte offsets)
    __shared__ int sA[2][NN];
    __shared__ int sB[2][NN];
    __shared__ int swA[NWARP], swB[NWARP];

    const int   c0k     = ct[n0];
    const int   c1k     = ct[n0 + 1];
    const int   entry0  = n0 * NN * 4;
    const int   entry1  = (n0 + 1) * NN * 4;

    float leak[NPT]    = {c0k ? 0.01f : 0.005f, c1k ? 0.01f : 0.005f};
    float refstep[NPT] = {c0k ? 1.0f : 2.0f,    c1k ? 1.0f : 2.0f};

    float U[NPT], x0[NPT], x1[NPT], x2[NPT], g0[NPT], g1[NPT], g2[NPT],
          xF[NPT], gF[NPT], ref[NPT];
#pragma unroll
    for (int k = 0; k < NPT; k++) {
        U[k] = -65.0f;
        x0[k] = x1[k] = x2[k] = g0[k] = g1[k] = g2[k] = xF[k] = gF[k] = ref[k] = 0.f;
    }

    const char* __restrict__ wb  = (const char*)d_Wsc + (size_t)n0 * 4;
    const float* __restrict__ ifp = d_IF + (size_t)b * TT * NN + n0;
    const size_t VOFF = (size_t)BB * TT * NN;
    const unsigned lt = (1u << lane) - 1u;

    int cntA = 0, cntB = 0;                     // spike counts from step t-1

    for (int t = 0; t < TT; t++) {
        const int wp = t & 1, rp = wp ^ 1;

        // FF drive (precomputed, streaming)
        float2 inFv = *(const float2*)__builtin_assume_aligned(ifp + (size_t)t * NN, 8);
        float inF0, inF1;
        {
            const float2 v = __ldcg((const float2*)(ifp + (size_t)t * NN));
            inF0 = v.x; inF1 = v.y; (void)inFv;
        }

        // -------- sparse recurrent gather (tiny lists, float2 per entry) ---
        float aAx0 = 0.f, aAy0 = 0.f, aAx1 = 0.f, aAy1 = 0.f;
        {
            int e = 0;
#pragma unroll 2
            for (; e + 1 < cntA; e += 2) {
                float2 w0 = *(const float2*)(wb + sA[rp][e]);
                float2 w1 = *(const float2*)(wb + sA[rp][e + 1]);
                aAx0 += w0.x; aAy0 += w0.y; aAx1 += w1.x; aAy1 += w1.y;
            }
            if (e < cntA) {
                float2 w0 = *(const float2*)(wb + sA[rp][e]);
                aAx0 += w0.x; aAy0 += w0.y;
            }
        }
        float aBx0 = 0.f, aBy0 = 0.f, aBx1 = 0.f, aBy1 = 0.f;
        {
            int e = 0;
#pragma unroll 2
            for (; e + 1 < cntB; e += 2) {
                float2 w0 = *(const float2*)(wb + sB[rp][e]);
                float2 w1 = *(const float2*)(wb + sB[rp][e + 1]);
                aBx0 += w0.x; aBy0 += w0.y; aBx1 += w1.x; aBy1 += w1.y;
            }
            if (e < cntB) {
                float2 w0 = *(const float2*)(wb + sB[rp][e]);
                aBx0 += w0.x; aBy0 += w0.y;
            }
        }
        float inA[NPT] = {aAx0 + aAx1, aAy0 + aAy1};
        float inB[NPT] = {aBx0 + aBx1, aBy0 + aBy1};
        float inF[NPT] = {inF0, inF1};
        float sv[NPT], uv[NPT];

        // -------- neuron update --------------------------------------------
#pragma unroll
        for (int k = 0; k < NPT; k++) {
            x0[k] = AR0 * x0[k] + inA[k];
            x1[k] = AR1 * x1[k] + inA[k];
            x2[k] = AR0 * x2[k] + inB[k];
            g0[k] = AD0 * g0[k] + x0[k];
            g1[k] = AD1 * g1[k] + x1[k];
            g2[k] = AD2 * g2[k] + x2[k];
            xF[k] = AR0 * xF[k] + inF[k];
            gF[k] = AD0 * gF[k] + xF[k];

            float gtot = g0[k] + 0.5f * g1[k] + g2[k] + gF[k];
            float gE   = -70.0f * g2[k];
            float Isyn = gE - gtot * U[k];
            float Un   = U[k] + leak[k] * (10.0f * (-65.0f - U[k]) + Isyn);
            if (ref[k] > 0.0f) Un = -65.0f;          // refractory clamp
            ref[k] = fmaxf(ref[k] - 1.0f, 0.0f);
            float s = ((Un + 50.0f) >= 0.0f) ? 1.0f : 0.0f;
            if (s > 0.0f) { Un = -65.0f; ref[k] = refstep[k]; }
            U[k] = Un;
            sv[k] = s;
            uv[k] = Un;
        }
        bool spk0 = sv[0] > 0.0f, spk1 = sv[1] > 0.0f;

        // outputs: spikes then volts, both (B,T,N)
        size_t o = ((size_t)b * TT + t) * NN + n0;
        *(float2*)(out + o)        = make_float2(sv[0], sv[1]);
        *(float2*)(out + VOFF + o) = make_float2(uv[0], uv[1]);

        // -------- ballot-ordered compaction into local smem lists ----------
        unsigned mA0 = __ballot_sync(0xFFFFFFFFu, spk0 && (c0k == 0));
        unsigned mB0 = __ballot_sync(0xFFFFFFFFu, spk0 && (c0k != 0));
        unsigned mA1 = __ballot_sync(0xFFFFFFFFu, spk1 && (c1k == 0));
        unsigned mB1 = __ballot_sync(0xFFFFFFFFu, spk1 && (c1k != 0));
        if (lane == 0) {
            swA[wid] = __popc(mA0) + __popc(mA1);
            swB[wid] = __popc(mB0) + __popc(mB1);
        }
        __syncthreads();                         // wcnts visible

        int baseA = 0, totA = 0, baseB = 0, totB = 0;
#pragma unroll
        for (int w2 = 0; w2 < NWARP; w2++) {
            int vA = swA[w2], vB = swB[w2];
            if (w2 < wid) { baseA += vA; baseB += vB; }
            totA += vA; totB += vB;
        }
        int a0full = __popc(mA0), b0full = __popc(mB0);
        if (spk0) {
            if (c0k == 0) sA[wp][baseA + __popc(mA0 & lt)] = entry0;
            else          sB[wp][baseB + __popc(mB0 & lt)] = entry0;
        }
        if (spk1) {
            if (c1k == 0) sA[wp][baseA + a0full + __popc(mA1 & lt)] = entry1;
            else          sB[wp][baseB + b0full + __popc(mB1 & lt)] = entry1;
        }
        cntA = totA;
        cntB = totB;
        __syncthreads();                         // lists ready for t+1
    }
}

// ------------------------- launcher -----------------------------------------
extern "C" void kernel_launch(void* const* d_in, const int* in_sizes, int n_in,
                              void* d_out, int out_size) {
    const float* input_spikes = (const float*)d_in[0]; // (B,T,NI)
    const float* weights      = (const float*)d_in[1]; // (NN,NN)
    const float* weights_FF   = (const float*)d_in[2]; // (NI,NN)
    const float* sf           = (const float*)d_in[3]; // (2,2)
    const float* sff          = (const float*)d_in[4]; // (1,2)
    const int*   ct           = (const int*)d_in[5];   // (NN,)
    (void)in_sizes; (void)n_in; (void)out_size;

    int total = NN * NN + NI * NN;
    scale_k<<<(total + 255) / 256, 256>>>(weights, weights_FF, sf, sff, ct);
    ffl_k<<<BB * TT, 32>>>(input_spikes);
    ffpre_k<<<dim3(NN / FCOLS, BB), FTPB>>>();
    sim_k<<<BB, TPB>>>(ct, (float*)d_out);
}

// round 5
// speedup vs baseline: 1.6117x; 1.6117x over previous
#include <cuda_runtime.h>
#include <cstdint>

// Problem constants (fixed by the reference)
#define BB 32
#define TT 256
#define NN 1536
#define NI 768

// Sim config: ONE CTA per batch, 768 threads, 2 neurons/thread.
#define TPB   768
#define NPT   2
#define NWARP (TPB / 32)

// exp constants, correctly rounded fp32
#define AR0 0.13533528323661270f   // exp(-2)    : rise tau 0.5 (syn0, syn2, FF)
#define AR1 0.60653065971263342f   // exp(-0.5)  : rise tau 2   (syn1)
#define AD0 0.60653065971263342f   // exp(-0.5)  : decay tau 2  (syn0, FF)
#define AD1 0.99004983374916805f   // exp(-0.01) : decay tau 100(syn1)
#define AD2 0.81873075307798186f   // exp(-0.2)  : decay tau 5  (syn2)

// ------------------------- device scratch (statics; no allocs) -------------
__device__ float d_Wsc[NN * NN];             // weights * sf[ct[n]][ct[m]]
__device__ float d_WFsc[NI * NN];            // weights_FF * sfF[ct[m]]
__device__ float d_IF[(size_t)BB * TT * NN]; // precomputed FF drive
__device__ int   d_ffcnt[BB * TT];           // input spike counts per (b,t)
__device__ int   d_fflist[BB * TT][NI];      // byte offsets j*NN*4

// ------------------------- weight scaling ----------------------------------
__global__ void scale_k(const float* __restrict__ w, const float* __restrict__ wff,
                        const float* __restrict__ sf, const float* __restrict__ sff,
                        const int* __restrict__ ct) {
    int idx = blockIdx.x * 256 + threadIdx.x;
    if (idx < NN * NN) {
        int n = idx / NN, m = idx % NN;
        d_Wsc[idx] = w[idx] * sf[ct[n] * 2 + ct[m]];
    } else {
        int r = idx - NN * NN;
        if (r < NI * NN) {
            int m = r % NN;
            d_WFsc[r] = wff[r] * sff[ct[m]];   // ct_FF is all zeros -> row 0
        }
    }
}

// ------------------------- FF spike lists (ballot-ordered, byte offsets) ---
__global__ void ffl_k(const float* __restrict__ inp) {
    int bt = blockIdx.x;                      // bt = b*TT + t
    int lane = threadIdx.x;
    const float* row = inp + (size_t)bt * NI;
    int cnt = 0;
    for (int base = 0; base < NI; base += 32) {
        float v = row[base + lane];
        unsigned m = __ballot_sync(0xFFFFFFFFu, v > 0.5f);
        if (v > 0.5f) {
            int p = cnt + __popc(m & ((1u << lane) - 1u));
            d_fflist[bt][p] = (base + lane) * NN * 4;   // byte offset of row
        }
        cnt += __popc(m);
    }
    if (lane == 0) d_ffcnt[bt] = cnt;
}

// ------------------------- FF drive precompute ------------------------------
// Grid = (batch, 64-col tile): adjacent blockIdx (co-resident on one SM at
// occupancy 2) share the SAME column tile -> one 196KB L1-resident slab per SM.
// 16 warps, each warp owns 16 timesteps; lanes cover 2 cols each (float2).
#define FCOLS 64
#define FTPB  512
__global__ void __launch_bounds__(FTPB, 2) ffpre_k() {
    int b  = blockIdx.x;
    int c0 = blockIdx.y * FCOLS;
    int w    = threadIdx.x >> 5;
    int lane = threadIdx.x & 31;
    const char* __restrict__ Wc =
        (const char*)d_WFsc + (size_t)(c0 + lane * 2) * 4;
#pragma unroll
    for (int ti = 0; ti < TT / 16; ti++) {
        int t  = w * 16 + ti;
        int bt = b * TT + t;
        int fc = d_ffcnt[bt];
        const int* __restrict__ lst = d_fflist[bt];
        float a0 = 0.f, a1 = 0.f, a2 = 0.f, a3 = 0.f;
        int e = 0;
#pragma unroll 4
        for (; e + 1 < fc; e += 2) {
            int o0 = lst[e], o1 = lst[e + 1];
            float2 v0 = *(const float2*)(Wc + o0);
            float2 v1 = *(const float2*)(Wc + o1);
            a0 += v0.x; a1 += v0.y; a2 += v1.x; a3 += v1.y;
        }
        if (e < fc) {
            float2 v = *(const float2*)(Wc + lst[e]);
            a0 += v.x; a1 += v.y;
        }
        *(float2*)&d_IF[(size_t)bt * NN + c0 + lane * 2] =
            make_float2(a0 + a2, a1 + a3);
    }
}

// ------------------------- main persistent simulator ------------------------
// grid = 32 (one CTA per batch), block = 768 (one thread per 2 neurons).
// Spike lists are CTA-local smem, ballot-ordered (deterministic). Warp counts
// packed A|(B<<16) in one smem word; 32-lane shuffle scan replaces the
// per-thread NWARP prefix loop. FF drive is prefetched one step ahead.
__global__ void __launch_bounds__(TPB, 1)
sim_k(const int* __restrict__ ct, float* __restrict__ out) {
    const int b    = blockIdx.x;
    const int tid  = threadIdx.x;
    const int wid  = tid >> 5, lane = tid & 31;
    const int n0   = tid * NPT;

    // double-buffered type-split spike lists (byte offsets)
    __shared__ int sA[2][NN];
    __shared__ int sB[2][NN];
    __shared__ int swAB[32];                   // packed warp counts (pad to 32)

    if (tid < 32) swAB[tid] = 0;               // lanes >= NWARP stay zero

    const int c0k    = ct[n0];
    const int c1k    = ct[n0 + 1];
    const int entry0 = n0 * NN * 4;
    const int entry1 = (n0 + 1) * NN * 4;

    float leak[NPT]    = {c0k ? 0.01f : 0.005f, c1k ? 0.01f : 0.005f};
    float refstep[NPT] = {c0k ? 1.0f : 2.0f,    c1k ? 1.0f : 2.0f};

    float U[NPT], x0[NPT], x1[NPT], x2[NPT], g0[NPT], g1[NPT], g2[NPT],
          xF[NPT], gF[NPT], ref[NPT];
#pragma unroll
    for (int k = 0; k < NPT; k++) {
        U[k] = -65.0f;
        x0[k] = x1[k] = x2[k] = g0[k] = g1[k] = g2[k] = xF[k] = gF[k] = ref[k] = 0.f;
    }

    const char* __restrict__ wb   = (const char*)d_Wsc + (size_t)n0 * 4;
    const float* __restrict__ ifp = d_IF + (size_t)b * TT * NN + n0;
    const size_t VOFF = (size_t)BB * TT * NN;
    const unsigned lt = (1u << lane) - 1u;

    int cntA = 0, cntB = 0;                    // spike counts from step t-1
    float2 ffcur = __ldcg((const float2*)ifp); // prefetched FF drive for t=0

    __syncthreads();                           // swAB init visible

    for (int t = 0; t < TT; t++) {
        const int wp = t & 1, rp = wp ^ 1;

        // prefetch FF drive for t+1 (hides DRAM latency behind this step)
        float2 ffnext = (t + 1 < TT)
            ? __ldcg((const float2*)(ifp + (size_t)(t + 1) * NN))
            : make_float2(0.f, 0.f);

        // -------- sparse recurrent gather (tiny lists, float2 per entry) ---
        float aAx0 = 0.f, aAy0 = 0.f, aAx1 = 0.f, aAy1 = 0.f;
        {
            int e = 0;
#pragma unroll 2
            for (; e + 1 < cntA; e += 2) {
                float2 w0 = *(const float2*)(wb + sA[rp][e]);
                float2 w1 = *(const float2*)(wb + sA[rp][e + 1]);
                aAx0 += w0.x; aAy0 += w0.y; aAx1 += w1.x; aAy1 += w1.y;
            }
            if (e < cntA) {
                float2 w0 = *(const float2*)(wb + sA[rp][e]);
                aAx0 += w0.x; aAy0 += w0.y;
            }
        }
        float aBx0 = 0.f, aBy0 = 0.f, aBx1 = 0.f, aBy1 = 0.f;
        {
            int e = 0;
#pragma unroll 2
            for (; e + 1 < cntB; e += 2) {
                float2 w0 = *(const float2*)(wb + sB[rp][e]);
                float2 w1 = *(const float2*)(wb + sB[rp][e + 1]);
                aBx0 += w0.x; aBy0 += w0.y; aBx1 += w1.x; aBy1 += w1.y;
            }
            if (e < cntB) {
                float2 w0 = *(const float2*)(wb + sB[rp][e]);
                aBx0 += w0.x; aBy0 += w0.y;
            }
        }
        float inA[NPT] = {aAx0 + aAx1, aAy0 + aAy1};
        float inB[NPT] = {aBx0 + aBx1, aBy0 + aBy1};
        float inF[NPT] = {ffcur.x, ffcur.y};
        ffcur = ffnext;
        float sv[NPT], uv[NPT];

        // -------- neuron update --------------------------------------------
#pragma unroll
        for (int k = 0; k < NPT; k++) {
            x0[k] = AR0 * x0[k] + inA[k];
            x1[k] = AR1 * x1[k] + inA[k];
            x2[k] = AR0 * x2[k] + inB[k];
            g0[k] = AD0 * g0[k] + x0[k];
            g1[k] = AD1 * g1[k] + x1[k];
            g2[k] = AD2 * g2[k] + x2[k];
            xF[k] = AR0 * xF[k] + inF[k];
            gF[k] = AD0 * gF[k] + xF[k];

            float gtot = g0[k] + 0.5f * g1[k] + g2[k] + gF[k];
            float gE   = -70.0f * g2[k];
            float Isyn = gE - gtot * U[k];
            float Un   = U[k] + leak[k] * (10.0f * (-65.0f - U[k]) + Isyn);
            if (ref[k] > 0.0f) Un = -65.0f;          // refractory clamp
            ref[k] = fmaxf(ref[k] - 1.0f, 0.0f);
            float s = ((Un + 50.0f) >= 0.0f) ? 1.0f : 0.0f;
            if (s > 0.0f) { Un = -65.0f; ref[k] = refstep[k]; }
            U[k] = Un;
            sv[k] = s;
            uv[k] = Un;
        }
        bool spk0 = sv[0] > 0.0f, spk1 = sv[1] > 0.0f;

        // outputs: spikes then volts, both (B,T,N)
        size_t o = ((size_t)b * TT + t) * NN + n0;
        *(float2*)(out + o)        = make_float2(sv[0], sv[1]);
        *(float2*)(out + VOFF + o) = make_float2(uv[0], uv[1]);

        // -------- ballot-ordered compaction (packed warp counts + scan) ----
        unsigned mA0 = __ballot_sync(0xFFFFFFFFu, spk0 && (c0k == 0));
        unsigned mB0 = __ballot_sync(0xFFFFFFFFu, spk0 && (c0k != 0));
        unsigned mA1 = __ballot_sync(0xFFFFFFFFu, spk1 && (c1k == 0));
        unsigned mB1 = __ballot_sync(0xFFFFFFFFu, spk1 && (c1k != 0));
        if (lane == 0)
            swAB[wid] = (__popc(mA0) + __popc(mA1)) |
                        ((__popc(mB0) + __popc(mB1)) << 16);
        __syncthreads();                         // (1) warp counts visible

        // every warp redundantly scans the 32 (padded) packed counts
        int v = swAB[lane];                      // lanes >= NWARP read 0
        int orig = v;
#pragma unroll
        for (int off = 1; off < 32; off <<= 1) {
            int u = __shfl_up_sync(0xFFFFFFFFu, v, off);
            if (lane >= off) v += u;
        }
        int incl  = __shfl_sync(0xFFFFFFFFu, v, wid);
        int own   = __shfl_sync(0xFFFFFFFFu, orig, wid);
        int tot   = __shfl_sync(0xFFFFFFFFu, v, 31);
        int base  = incl - own;                  // exclusive prefix (packed)
        int baseA = base & 0xFFFF, baseB = base >> 16;

        int a0full = __popc(mA0), b0full = __popc(mB0);
        if (spk0) {
            if (c0k == 0) sA[wp][baseA + __popc(mA0 & lt)] = entry0;
            else          sB[wp][baseB + __popc(mB0 & lt)] = entry0;
        }
        if (spk1) {
            if (c1k == 0) sA[wp][baseA + a0full + __popc(mA1 & lt)] = entry1;
            else          sB[wp][baseB + b0full + __popc(mB1 & lt)] = entry1;
        }
        cntA = tot & 0xFFFF;
        cntB = tot >> 16;
        __syncthreads();                         // (2) lists ready for t+1
    }
}

// ------------------------- launcher -----------------------------------------
extern "C" void kernel_launch(void* const* d_in, const int* in_sizes, int n_in,
                              void* d_out, int out_size) {
    const float* input_spikes = (const float*)d_in[0]; // (B,T,NI)
    const float* weights      = (const float*)d_in[1]; // (NN,NN)
    const float* weights_FF   = (const float*)d_in[2]; // (NI,NN)
    const float* sf           = (const float*)d_in[3]; // (2,2)
    const float* sff          = (const float*)d_in[4]; // (1,2)
    const int*   ct           = (const int*)d_in[5];   // (NN,)
    (void)in_sizes; (void)n_in; (void)out_size;

    int total = NN * NN + NI * NN;
    scale_k<<<(total + 255) / 256, 256>>>(weights, weights_FF, sf, sff, ct);
    ffl_k<<<BB * TT, 32>>>(input_spikes);
    ffpre_k<<<dim3(BB, NN / FCOLS), FTPB>>>();
    sim_k<<<BB, TPB>>>(ct, (float*)d_out);
}

// round 6
// speedup vs baseline: 1.7034x; 1.0569x over previous
#include <cuda_runtime.h>
#include <cstdint>

// Problem constants (fixed by the reference)
#define BB 32
#define TT 256
#define NN 1536
#define NI 768

// Sim config: ONE CTA per batch, 384 threads, 4 neurons/thread.
#define TPB   384
#define NPT   4
#define NWARP (TPB / 32)

// exp constants, correctly rounded fp32
#define AR0 0.13533528323661270f   // exp(-2)    : rise tau 0.5 (syn0, syn2, FF)
#define AR1 0.60653065971263342f   // exp(-0.5)  : rise tau 2   (syn1)
#define AD0 0.60653065971263342f   // exp(-0.5)  : decay tau 2  (syn0, FF)
#define AD1 0.99004983374916805f   // exp(-0.01) : decay tau 100(syn1)
#define AD2 0.81873075307798186f   // exp(-0.2)  : decay tau 5  (syn2)

// ------------------------- device scratch (statics; no allocs) -------------
__device__ float d_Wsc[NN * NN];             // weights * sf[ct[n]][ct[m]]
__device__ float d_WFsc[NI * NN];            // weights_FF * sfF[ct[m]]
__device__ float d_IF[(size_t)BB * TT * NN]; // precomputed FF drive
__device__ int   d_ffcnt[BB * TT];           // input spike counts per (b,t)
__device__ int   d_fflist[BB * TT][NI];      // byte offsets j*NN*4

// ------------------------- packed f32x2 helpers -----------------------------
typedef unsigned long long u64;
__device__ __forceinline__ u64 pk2(float lo, float hi) {
    u64 r; asm("mov.b64 %0, {%1,%2};" : "=l"(r) : "f"(lo), "f"(hi)); return r;
}
__device__ __forceinline__ void upk2(float& lo, float& hi, u64 v) {
    asm("mov.b64 {%0,%1}, %2;" : "=f"(lo), "=f"(hi) : "l"(v));
}
__device__ __forceinline__ u64 fma2(u64 a, u64 b, u64 c) {
    u64 d; asm("fma.rn.f32x2 %0, %1, %2, %3;" : "=l"(d) : "l"(a), "l"(b), "l"(c));
    return d;
}
__device__ __forceinline__ u64 add2(u64 a, u64 b) {
    u64 d; asm("add.rn.f32x2 %0, %1, %2;" : "=l"(d) : "l"(a), "l"(b)); return d;
}
__device__ __forceinline__ u64 mul2(u64 a, u64 b) {
    u64 d; asm("mul.rn.f32x2 %0, %1, %2;" : "=l"(d) : "l"(a), "l"(b)); return d;
}

// ------------------------- weight scaling ----------------------------------
__global__ void scale_k(const float* __restrict__ w, const float* __restrict__ wff,
                        const float* __restrict__ sf, const float* __restrict__ sff,
                        const int* __restrict__ ct) {
    int idx = blockIdx.x * 256 + threadIdx.x;
    if (idx < NN * NN) {
        int n = idx / NN, m = idx % NN;
        d_Wsc[idx] = w[idx] * sf[ct[n] * 2 + ct[m]];
    } else {
        int r = idx - NN * NN;
        if (r < NI * NN) {
            int m = r % NN;
            d_WFsc[r] = wff[r] * sff[ct[m]];   // ct_FF is all zeros -> row 0
        }
    }
}

// ------------------------- FF spike lists (ballot-ordered, byte offsets) ---
__global__ void ffl_k(const float* __restrict__ inp) {
    int bt = blockIdx.x;                      // bt = b*TT + t
    int lane = threadIdx.x;
    const float* row = inp + (size_t)bt * NI;
    int cnt = 0;
    for (int base = 0; base < NI; base += 32) {
        float v = row[base + lane];
        unsigned m = __ballot_sync(0xFFFFFFFFu, v > 0.5f);
        if (v > 0.5f) {
            int p = cnt + __popc(m & ((1u << lane) - 1u));
            d_fflist[bt][p] = (base + lane) * NN * 4;   // byte offset of row
        }
        cnt += __popc(m);
    }
    if (lane == 0) d_ffcnt[bt] = cnt;
}

// ------------------------- FF drive precompute ------------------------------
// Grid = (batch, 64-col tile): adjacent blockIdx (co-resident on one SM at
// occupancy 2) share the SAME column tile -> one 196KB L1-resident slab per SM.
#define FCOLS 64
#define FTPB  512
__global__ void __launch_bounds__(FTPB, 2) ffpre_k() {
    int b  = blockIdx.x;
    int c0 = blockIdx.y * FCOLS;
    int w    = threadIdx.x >> 5;
    int lane = threadIdx.x & 31;
    const char* __restrict__ Wc =
        (const char*)d_WFsc + (size_t)(c0 + lane * 2) * 4;
#pragma unroll
    for (int ti = 0; ti < TT / 16; ti++) {
        int t  = w * 16 + ti;
        int bt = b * TT + t;
        int fc = d_ffcnt[bt];
        const int* __restrict__ lst = d_fflist[bt];
        float a0 = 0.f, a1 = 0.f, a2 = 0.f, a3 = 0.f;
        int e = 0;
#pragma unroll 4
        for (; e + 1 < fc; e += 2) {
            int o0 = lst[e], o1 = lst[e + 1];
            float2 v0 = *(const float2*)(Wc + o0);
            float2 v1 = *(const float2*)(Wc + o1);
            a0 += v0.x; a1 += v0.y; a2 += v1.x; a3 += v1.y;
        }
        if (e < fc) {
            float2 v = *(const float2*)(Wc + lst[e]);
            a0 += v.x; a1 += v.y;
        }
        *(float2*)&d_IF[(size_t)bt * NN + c0 + lane * 2] =
            make_float2(a0 + a2, a1 + a3);
    }
}

// ------------------------- main persistent simulator ------------------------
// grid = 32 (one CTA per batch), block = 384 (one thread per 4 neurons).
// Issue-bound design: packed f32x2 updates, LDG.128 gathers, static type
// masks, 12-warp shuffle scan, double-buffered type-split lists.
__global__ void __launch_bounds__(TPB, 1)
sim_k(const int* __restrict__ ct, float* __restrict__ out) {
    const int b    = blockIdx.x;
    const int tid  = threadIdx.x;
    const int wid  = tid >> 5, lane = tid & 31;
    const int n0   = tid * NPT;

    // double-buffered type-split spike lists (byte offsets)
    __shared__ int sA[2][NN];
    __shared__ int sB[2][NN];
    __shared__ int swAB[16];                   // packed warp counts (pad to 16)

    if (tid < 16) swAB[tid] = 0;               // lanes >= NWARP stay zero

    int4 ctv = *(const int4*)(ct + n0);
    const int ctk[NPT] = {ctv.x, ctv.y, ctv.z, ctv.w};

    // static per-warp cell-type masks (ballot over constant predicate)
    unsigned cA[NPT];
#pragma unroll
    for (int k = 0; k < NPT; k++)
        cA[k] = __ballot_sync(0xFFFFFFFFu, ctk[k] == 0);

    float leak[NPT], refstep[NPT];
#pragma unroll
    for (int k = 0; k < NPT; k++) {
        leak[k]    = ctk[k] ? 0.01f : 0.005f;
        refstep[k] = ctk[k] ? 1.0f : 2.0f;
    }
    const u64 leakp[2] = {pk2(leak[0], leak[1]), pk2(leak[2], leak[3])};

    // packed constants
    const u64 AR0p = pk2(AR0, AR0), AR1p = pk2(AR1, AR1);
    const u64 AD0p = pk2(AD0, AD0), AD1p = pk2(AD1, AD1), AD2p = pk2(AD2, AD2);
    const u64 HALFp = pk2(0.5f, 0.5f), M70p = pk2(-70.f, -70.f);
    const u64 M65p  = pk2(-65.f, -65.f), TENp = pk2(10.f, 10.f);

    // packed state (pairs {k0,k1} and {k2,k3})
    u64 X0[2], X1[2], X2[2], G0[2], G1[2], G2[2], XF[2], GF[2];
    float U[NPT], ref[NPT];
#pragma unroll
    for (int p = 0; p < 2; p++)
        X0[p] = X1[p] = X2[p] = G0[p] = G1[p] = G2[p] = XF[p] = GF[p] = 0ull;
#pragma unroll
    for (int k = 0; k < NPT; k++) { U[k] = -65.0f; ref[k] = 0.f; }

    const char* __restrict__ wb   = (const char*)d_Wsc + (size_t)n0 * 4;
    const float* __restrict__ ifp = d_IF + (size_t)b * TT * NN + n0;
    const size_t VOFF = (size_t)BB * TT * NN;
    const unsigned lt = (1u << lane) - 1u;

    int cntA = 0, cntB = 0;                    // spike counts from step t-1
    float4 ffcur = __ldcg((const float4*)ifp); // prefetched FF drive for t=0

    __syncthreads();                           // swAB init visible

    for (int t = 0; t < TT; t++) {
        const int wp = t & 1, rp = wp ^ 1;

        // prefetch FF drive for t+1 (hides DRAM latency behind this step)
        float4 ffnext = (t + 1 < TT)
            ? __ldcg((const float4*)(ifp + (size_t)(t + 1) * NN))
            : make_float4(0.f, 0.f, 0.f, 0.f);

        // -------- sparse recurrent gather (LDG.128 per entry) --------------
        float a0 = 0.f, a1 = 0.f, a2 = 0.f, a3 = 0.f;
        {
            int e = 0;
#pragma unroll 2
            for (; e + 1 < cntA; e += 2) {
                float4 w0 = *(const float4*)(wb + sA[rp][e]);
                float4 w1 = *(const float4*)(wb + sA[rp][e + 1]);
                a0 += w0.x; a1 += w0.y; a2 += w0.z; a3 += w0.w;
                a0 += w1.x; a1 += w1.y; a2 += w1.z; a3 += w1.w;
            }
            if (e < cntA) {
                float4 w0 = *(const float4*)(wb + sA[rp][e]);
                a0 += w0.x; a1 += w0.y; a2 += w0.z; a3 += w0.w;
            }
        }
        float b0 = 0.f, b1 = 0.f, b2 = 0.f, b3 = 0.f;
        {
            int e = 0;
#pragma unroll 2
            for (; e + 1 < cntB; e += 2) {
                float4 w0 = *(const float4*)(wb + sB[rp][e]);
                float4 w1 = *(const float4*)(wb + sB[rp][e + 1]);
                b0 += w0.x; b1 += w0.y; b2 += w0.z; b3 += w0.w;
                b0 += w1.x; b1 += w1.y; b2 += w1.z; b3 += w1.w;
            }
            if (e < cntB) {
                float4 w0 = *(const float4*)(wb + sB[rp][e]);
                b0 += w0.x; b1 += w0.y; b2 += w0.z; b3 += w0.w;
            }
        }
        const u64 inAp[2] = {pk2(a0, a1), pk2(a2, a3)};
        const u64 inBp[2] = {pk2(b0, b1), pk2(b2, b3)};
        const u64 inFp[2] = {pk2(ffcur.x, ffcur.y), pk2(ffcur.z, ffcur.w)};
        ffcur = ffnext;

        // -------- neuron update (packed filters + membrane) ----------------
        float sv[NPT], uv[NPT];
#pragma unroll
        for (int p = 0; p < 2; p++) {
            X0[p] = fma2(AR0p, X0[p], inAp[p]);
            X1[p] = fma2(AR1p, X1[p], inAp[p]);
            X2[p] = fma2(AR0p, X2[p], inBp[p]);
            G0[p] = fma2(AD0p, G0[p], X0[p]);
            G1[p] = fma2(AD1p, G1[p], X1[p]);
            G2[p] = fma2(AD2p, G2[p], X2[p]);
            XF[p] = fma2(AR0p, XF[p], inFp[p]);
            GF[p] = fma2(AD0p, GF[p], XF[p]);

            // gtot = g0 + 0.5*g1 + g2 + gF ; gE = -70*g2
            u64 gtot = add2(fma2(HALFp, G1[p], G0[p]), add2(G2[p], GF[p]));
            u64 gE   = mul2(M70p, G2[p]);
            // packed U / -U for this pair
            float u0 = U[p * 2], u1 = U[p * 2 + 1];
            u64 Up  = pk2(u0, u1);
            u64 nUp = pk2(-u0, -u1);
            // Isyn = gE - gtot*U ; s1 = -65 - U ; s2 = 10*s1 + Isyn
            u64 Isyn = fma2(gtot, nUp, gE);
            u64 s1   = add2(M65p, nUp);
            u64 s2   = fma2(TENp, s1, Isyn);
            u64 Unp  = fma2(leakp[p], s2, Up);

            float Un0, Un1;
            upk2(Un0, Un1, Unp);
            float Unk[2] = {Un0, Un1};
#pragma unroll
            for (int q = 0; q < 2; q++) {
                int k = p * 2 + q;
                float Un = Unk[q];
                if (ref[k] > 0.0f) Un = -65.0f;      // refractory clamp
                ref[k] = fmaxf(ref[k] - 1.0f, 0.0f);
                float s = ((Un + 50.0f) >= 0.0f) ? 1.0f : 0.0f;
                if (s > 0.0f) { Un = -65.0f; ref[k] = refstep[k]; }
                U[k] = Un;
                sv[k] = s;
                uv[k] = Un;
            }
        }

        // outputs: spikes then volts, both (B,T,N)
        size_t o = ((size_t)b * TT + t) * NN + n0;
        *(float4*)(out + o)        = make_float4(sv[0], sv[1], sv[2], sv[3]);
        *(float4*)(out + VOFF + o) = make_float4(uv[0], uv[1], uv[2], uv[3]);

        // -------- ballot-ordered compaction (static type masks) ------------
        unsigned mA[NPT], mB[NPT];
        int cA_w = 0, cB_w = 0;
#pragma unroll
        for (int k = 0; k < NPT; k++) {
            unsigned mk = __ballot_sync(0xFFFFFFFFu, sv[k] > 0.0f);
            mA[k] = mk & cA[k];
            mB[k] = mk & ~cA[k];
            cA_w += __popc(mA[k]);
            cB_w += __popc(mB[k]);
        }
        if (lane == 0) swAB[wid] = cA_w | (cB_w << 16);
        __syncthreads();                         // (1) warp counts visible

        // every warp redundantly scans the 16 (padded) packed counts
        int v = (lane < 16) ? swAB[lane] : 0;
        int orig = v;
#pragma unroll
        for (int off = 1; off < 16; off <<= 1) {
            int u = __shfl_up_sync(0xFFFFFFFFu, v, off);
            if (lane >= off) v += u;
        }
        int incl = __shfl_sync(0xFFFFFFFFu, v, wid);
        int own  = __shfl_sync(0xFFFFFFFFu, orig, wid);
        int tot  = __shfl_sync(0xFFFFFFFFu, v, 15);
        int base = incl - own;                   // exclusive prefix (packed)
        int baseA = base & 0xFFFF, baseB = base >> 16;

        int preA = 0, preB = 0;
#pragma unroll
        for (int k = 0; k < NPT; k++) {
            if (sv[k] > 0.0f) {
                int entry = (n0 + k) * NN * 4;
                if (ctk[k] == 0)
                    sA[wp][baseA + preA + __popc(mA[k] & lt)] = entry;
                else
                    sB[wp][baseB + preB + __popc(mB[k] & lt)] = entry;
            }
            preA += __popc(mA[k]);
            preB += __popc(mB[k]);
        }
        cntA = tot & 0xFFFF;
        cntB = tot >> 16;
        __syncthreads();                         // (2) lists ready for t+1
    }
}

// ------------------------- launcher -----------------------------------------
extern "C" void kernel_launch(void* const* d_in, const int* in_sizes, int n_in,
                              void* d_out, int out_size) {
    const float* input_spikes = (const float*)d_in[0]; // (B,T,NI)
    const float* weights      = (const float*)d_in[1]; // (NN,NN)
    const float* weights_FF   = (const float*)d_in[2]; // (NI,NN)
    const float* sf           = (const float*)d_in[3]; // (2,2)
    const float* sff          = (const float*)d_in[4]; // (1,2)
    const int*   ct           = (const int*)d_in[5];   // (NN,)
    (void)in_sizes; (void)n_in; (void)out_size;

    int total = NN * NN + NI * NN;
    scale_k<<<(total + 255) / 256, 256>>>(weights, weights_FF, sf, sff, ct);
    ffl_k<<<BB * TT, 32>>>(input_spikes);
    ffpre_k<<<dim3(BB, NN / FCOLS), FTPB>>>();
    sim_k<<<BB, TPB>>>(ct, (float*)d_out);
}